// round 2
// baseline (speedup 1.0000x reference)
#include <cuda_runtime.h>

#define N_NODES 100000
#define N_EDGES 3200000
#define N_QUADS (N_EDGES / 4)

// ---------------- scratch (device globals; no allocation allowed) ----------
__device__ float  g_deg[N_NODES];
__device__ float  g_dinv[N_NODES];
__device__ float2 g_agg1[N_NODES];
__device__ float2 g_z[N_NODES];

// Vector f32x2 reduction to global (PTX 8.1+, sm_90+). Halves atomic op count.
__device__ __forceinline__ void red_add_v2(float2* addr, float a, float b) {
    asm volatile("red.global.add.v2.f32 [%0], {%1, %2};"
                 :: "l"(addr), "f"(a), "f"(b) : "memory");
}

// K1: init degree to 1.0 (self-loop) and zero layer-1 aggregation buffer.
__global__ void k_init() {
    int n = blockIdx.x * blockDim.x + threadIdx.x;
    if (n < N_NODES) {
        g_deg[n]  = 1.0f;
        g_agg1[n] = make_float2(0.0f, 0.0f);
    }
}

// K2: degree accumulation at destinations. 4 edges per thread via int4.
__global__ void k_degree(const int* __restrict__ dst) {
    int i = blockIdx.x * blockDim.x + threadIdx.x;   // quad index
    if (i < N_QUADS) {
        int4 d = reinterpret_cast<const int4*>(dst)[i];
        atomicAdd(&g_deg[d.x], 1.0f);
        atomicAdd(&g_deg[d.y], 1.0f);
        atomicAdd(&g_deg[d.z], 1.0f);
        atomicAdd(&g_deg[d.w], 1.0f);
    }
}

// K3: dinv = rsqrt(deg). deg >= 1 always (self-loop), so no zero guard needed.
__global__ void k_dinv() {
    int n = blockIdx.x * blockDim.x + threadIdx.x;
    if (n < N_NODES) g_dinv[n] = rsqrtf(g_deg[n]);
}

// K4: layer-1 edge aggregation in 2-dim input space: agg1[d] += norm * x[s].
__global__ void k_agg1(const int* __restrict__ src,
                       const int* __restrict__ dst,
                       const float* __restrict__ x) {
    int i = blockIdx.x * blockDim.x + threadIdx.x;
    if (i < N_QUADS) {
        int4 s = reinterpret_cast<const int4*>(src)[i];
        int4 d = reinterpret_cast<const int4*>(dst)[i];
        float n0 = g_dinv[s.x] * g_dinv[d.x];
        float n1 = g_dinv[s.y] * g_dinv[d.y];
        float n2 = g_dinv[s.z] * g_dinv[d.z];
        float n3 = g_dinv[s.w] * g_dinv[d.w];
        float2 x0 = reinterpret_cast<const float2*>(x)[s.x];
        float2 x1 = reinterpret_cast<const float2*>(x)[s.y];
        float2 x2 = reinterpret_cast<const float2*>(x)[s.z];
        float2 x3 = reinterpret_cast<const float2*>(x)[s.w];
        red_add_v2(&g_agg1[d.x], n0 * x0.x, n0 * x0.y);
        red_add_v2(&g_agg1[d.y], n1 * x1.x, n1 * x1.y);
        red_add_v2(&g_agg1[d.z], n2 * x2.x, n2 * x2.y);
        red_add_v2(&g_agg1[d.w], n3 * x3.x, n3 * x3.y);
    }
}

// K5: per-node fused dense chain.
//   a  = agg1[n] + dinv^2 * x[n]        (finish layer-1 aggregation w/ self-loop)
//   h  = relu(a @ W1^T + b1)            (64-dim, registers only)
//   z  = h @ W2^T                       (2-dim)
//   out[n] = b2 + dinv^2 * z            (layer-2 self-loop + bias; inits d_out)
__global__ void k_node(const float* __restrict__ x,
                       const float* __restrict__ W1,
                       const float* __restrict__ b1,
                       const float* __restrict__ W2,
                       const float* __restrict__ b2,
                       float2* __restrict__ out) {
    __shared__ float sW1[128];   // W1 row-major [64,2]
    __shared__ float sb1[64];
    __shared__ float sW2[128];   // W2 row-major [2,64]
    int t = threadIdx.x;
    if (t < 128)              sW1[t]       = W1[t];
    if (t < 64)               sb1[t]       = b1[t];
    if (t >= 128 && t < 256)  sW2[t - 128] = W2[t - 128];
    __syncthreads();

    int n = blockIdx.x * blockDim.x + t;
    if (n >= N_NODES) return;

    float  di  = g_dinv[n];
    float  di2 = di * di;
    float2 xv  = reinterpret_cast<const float2*>(x)[n];
    float2 a   = g_agg1[n];
    a.x = fmaf(di2, xv.x, a.x);
    a.y = fmaf(di2, xv.y, a.y);

    float zx = 0.0f, zy = 0.0f;
#pragma unroll
    for (int j = 0; j < 64; j++) {
        float h = fmaf(sW1[2 * j], a.x, fmaf(sW1[2 * j + 1], a.y, sb1[j]));
        h = fmaxf(h, 0.0f);
        zx = fmaf(sW2[j],      h, zx);
        zy = fmaf(sW2[64 + j], h, zy);
    }
    g_z[n] = make_float2(zx, zy);
    float bb0 = __ldg(&b2[0]), bb1 = __ldg(&b2[1]);
    out[n] = make_float2(fmaf(di2, zx, bb0), fmaf(di2, zy, bb1));
}

// K6: layer-2 edge aggregation: out[d] += norm * z[s].
__global__ void k_agg2(const int* __restrict__ src,
                       const int* __restrict__ dst,
                       float2* __restrict__ out) {
    int i = blockIdx.x * blockDim.x + threadIdx.x;
    if (i < N_QUADS) {
        int4 s = reinterpret_cast<const int4*>(src)[i];
        int4 d = reinterpret_cast<const int4*>(dst)[i];
        float n0 = g_dinv[s.x] * g_dinv[d.x];
        float n1 = g_dinv[s.y] * g_dinv[d.y];
        float n2 = g_dinv[s.z] * g_dinv[d.z];
        float n3 = g_dinv[s.w] * g_dinv[d.w];
        float2 z0 = g_z[s.x];
        float2 z1 = g_z[s.y];
        float2 z2 = g_z[s.z];
        float2 z3 = g_z[s.w];
        red_add_v2(&out[d.x], n0 * z0.x, n0 * z0.y);
        red_add_v2(&out[d.y], n1 * z1.x, n1 * z1.y);
        red_add_v2(&out[d.z], n2 * z2.x, n2 * z2.y);
        red_add_v2(&out[d.w], n3 * z3.x, n3 * z3.y);
    }
}

extern "C" void kernel_launch(void* const* d_in, const int* in_sizes, int n_in,
                              void* d_out, int out_size) {
    const float* x  = (const float*)d_in[0];
    const int*   ei = (const int*)d_in[1];
    const float* W1 = (const float*)d_in[2];
    const float* b1 = (const float*)d_in[3];
    const float* W2 = (const float*)d_in[4];
    const float* b2 = (const float*)d_in[5];
    float2*      out = (float2*)d_out;

    const int* src = ei;
    const int* dst = ei + N_EDGES;

    const int TB = 256;
    int nb_nodes = (N_NODES + TB - 1) / TB;
    int nb_quads = (N_QUADS + TB - 1) / TB;

    k_init  <<<nb_nodes, TB>>>();
    k_degree<<<nb_quads, TB>>>(dst);
    k_dinv  <<<nb_nodes, TB>>>();
    k_agg1  <<<nb_quads, TB>>>(src, dst, x);
    k_node  <<<nb_nodes, TB>>>(x, W1, b1, W2, b2, out);
    k_agg2  <<<nb_quads, TB>>>(src, dst, out);
}

// round 3
// speedup vs baseline: 1.3339x; 1.3339x over previous
#include <cuda_runtime.h>

#define N_NODES 100000
#define N_EDGES 3200000
#define N_QUADS (N_EDGES / 4)

// ---------------- scratch (device globals; no allocation allowed) ----------
__device__ float  g_deg[N_NODES];
__device__ float  g_dinv[N_NODES];
__device__ float2 g_y[N_NODES];      // dinv[n] * x[n]      (layer-1 source msgs)
__device__ float2 g_agg1[N_NODES];   // (A+I) @ y
__device__ float2 g_zs[N_NODES];     // dinv[n] * z[n]      (layer-2 source msgs)

// Vector f32x2 reduction to global (PTX 8.1+, sm_90+). Halves atomic op count.
__device__ __forceinline__ void red_add_v2(float2* addr, float a, float b) {
    asm volatile("red.global.add.v2.f32 [%0], {%1, %2};"
                 :: "l"(addr), "f"(a), "f"(b) : "memory");
}

// K1: degree init (self-loop contributes 1).
__global__ void k_init() {
    int n = blockIdx.x * blockDim.x + threadIdx.x;
    if (n < N_NODES) g_deg[n] = 1.0f;
}

// K2: degree accumulation at destinations. 4 edges per thread via int4.
__global__ void k_degree(const int* __restrict__ dst) {
    int i = blockIdx.x * blockDim.x + threadIdx.x;
    if (i < N_QUADS) {
        int4 d = reinterpret_cast<const int4*>(dst)[i];
        atomicAdd(&g_deg[d.x], 1.0f);
        atomicAdd(&g_deg[d.y], 1.0f);
        atomicAdd(&g_deg[d.z], 1.0f);
        atomicAdd(&g_deg[d.w], 1.0f);
    }
}

// K3: dinv = rsqrt(deg); y = dinv * x; agg1 init with self-loop term y[n].
__global__ void k_prescale(const float* __restrict__ x) {
    int n = blockIdx.x * blockDim.x + threadIdx.x;
    if (n < N_NODES) {
        float di = rsqrtf(g_deg[n]);
        g_dinv[n] = di;
        float2 xv = reinterpret_cast<const float2*>(x)[n];
        float2 y  = make_float2(di * xv.x, di * xv.y);
        g_y[n]    = y;
        g_agg1[n] = y;
    }
}

// K4: layer-1 aggregation: agg1[d] += y[s]. 2 wavefronts per edge.
__global__ void k_agg1(const int* __restrict__ src,
                       const int* __restrict__ dst) {
    int i = blockIdx.x * blockDim.x + threadIdx.x;
    if (i < N_QUADS) {
        int4 s = reinterpret_cast<const int4*>(src)[i];
        int4 d = reinterpret_cast<const int4*>(dst)[i];
        float2 y0 = g_y[s.x];
        float2 y1 = g_y[s.y];
        float2 y2 = g_y[s.z];
        float2 y3 = g_y[s.w];
        red_add_v2(&g_agg1[d.x], y0.x, y0.y);
        red_add_v2(&g_agg1[d.y], y1.x, y1.y);
        red_add_v2(&g_agg1[d.z], y2.x, y2.y);
        red_add_v2(&g_agg1[d.w], y3.x, y3.y);
    }
}

// K5: per-node fused dense chain.
//   a  = dinv[n] * agg1[n]              (destination post-scale, layer 1)
//   h  = relu(a @ W1^T + b1)            (64-dim, registers only)
//   z  = h @ W2^T                       (2-dim)
//   zs = dinv[n] * z                    (source pre-scale, layer 2)
//   out[n] = zs                         (self-loop init of layer-2 aggregation)
__global__ void k_node(const float* __restrict__ W1,
                       const float* __restrict__ b1,
                       const float* __restrict__ W2,
                       float2* __restrict__ out) {
    __shared__ float sW1[128];   // W1 row-major [64,2]
    __shared__ float sb1[64];
    __shared__ float sW2[128];   // W2 row-major [2,64]
    int t = threadIdx.x;
    if (t < 128)              sW1[t]       = W1[t];
    if (t < 64)               sb1[t]       = b1[t];
    if (t >= 128 && t < 256)  sW2[t - 128] = W2[t - 128];
    __syncthreads();

    int n = blockIdx.x * blockDim.x + t;
    if (n >= N_NODES) return;

    float  di = g_dinv[n];
    float2 ag = g_agg1[n];
    float  ax = di * ag.x, ay = di * ag.y;

    float zx = 0.0f, zy = 0.0f;
#pragma unroll
    for (int j = 0; j < 64; j++) {
        float h = fmaf(sW1[2 * j], ax, fmaf(sW1[2 * j + 1], ay, sb1[j]));
        h = fmaxf(h, 0.0f);
        zx = fmaf(sW2[j],      h, zx);
        zy = fmaf(sW2[64 + j], h, zy);
    }
    float2 zs = make_float2(di * zx, di * zy);
    g_zs[n] = zs;
    out[n]  = zs;
}

// K6: layer-2 aggregation directly into d_out: out[d] += zs[s].
__global__ void k_agg2(const int* __restrict__ src,
                       const int* __restrict__ dst,
                       float2* __restrict__ out) {
    int i = blockIdx.x * blockDim.x + threadIdx.x;
    if (i < N_QUADS) {
        int4 s = reinterpret_cast<const int4*>(src)[i];
        int4 d = reinterpret_cast<const int4*>(dst)[i];
        float2 z0 = g_zs[s.x];
        float2 z1 = g_zs[s.y];
        float2 z2 = g_zs[s.z];
        float2 z3 = g_zs[s.w];
        red_add_v2(&out[d.x], z0.x, z0.y);
        red_add_v2(&out[d.y], z1.x, z1.y);
        red_add_v2(&out[d.z], z2.x, z2.y);
        red_add_v2(&out[d.w], z3.x, z3.y);
    }
}

// K7: destination post-scale + bias: out[n] = dinv[n]*out[n] + b2.
__global__ void k_final(const float* __restrict__ b2,
                        float2* __restrict__ out) {
    int n = blockIdx.x * blockDim.x + threadIdx.x;
    if (n < N_NODES) {
        float di = g_dinv[n];
        float2 o = out[n];
        float bb0 = __ldg(&b2[0]), bb1 = __ldg(&b2[1]);
        out[n] = make_float2(fmaf(di, o.x, bb0), fmaf(di, o.y, bb1));
    }
}

extern "C" void kernel_launch(void* const* d_in, const int* in_sizes, int n_in,
                              void* d_out, int out_size) {
    const float* x  = (const float*)d_in[0];
    const int*   ei = (const int*)d_in[1];
    const float* W1 = (const float*)d_in[2];
    const float* b1 = (const float*)d_in[3];
    const float* W2 = (const float*)d_in[4];
    const float* b2 = (const float*)d_in[5];
    float2*      out = (float2*)d_out;

    const int* src = ei;
    const int* dst = ei + N_EDGES;

    const int TB = 256;
    int nb_nodes = (N_NODES + TB - 1) / TB;
    int nb_quads = (N_QUADS + TB - 1) / TB;

    k_init    <<<nb_nodes, TB>>>();
    k_degree  <<<nb_quads, TB>>>(dst);
    k_prescale<<<nb_nodes, TB>>>(x);
    k_agg1    <<<nb_quads, TB>>>(src, dst);
    k_node    <<<nb_nodes, TB>>>(W1, b1, W2, out);
    k_agg2    <<<nb_quads, TB>>>(src, dst, out);
    k_final   <<<nb_nodes, TB>>>(b2, out);
}

// round 4
// speedup vs baseline: 1.4167x; 1.0621x over previous
#include <cuda_runtime.h>
#include <cuda_fp16.h>

#define N_NODES 100000
#define N_EDGES 3200000
#define N_QUADS (N_EDGES / 4)

// ---------------- scratch (device globals; no allocation allowed) ----------
__device__ float   g_deg[N_NODES];
__device__ float   g_dinv[N_NODES];
__device__ __half2 g_y[N_NODES];     // f16x2(dinv[n] * x[n])   layer-1 source msgs
__device__ float2  g_agg1[N_NODES];  // (A+I) @ y               f32 accumulation
__device__ __half2 g_zs[N_NODES];    // f16x2(dinv[n] * z[n])   layer-2 source msgs

// Vector f32x2 reduction to global (PTX 8.1+, sm_90+). Halves atomic op count.
__device__ __forceinline__ void red_add_v2(float2* addr, float a, float b) {
    asm volatile("red.global.add.v2.f32 [%0], {%1, %2};"
                 :: "l"(addr), "f"(a), "f"(b) : "memory");
}

// K1: degree init (self-loop contributes 1).
__global__ void k_init() {
    int n = blockIdx.x * blockDim.x + threadIdx.x;
    if (n < N_NODES) g_deg[n] = 1.0f;
}

// K2: degree accumulation at destinations. 4 edges per thread via int4.
__global__ void k_degree(const int* __restrict__ dst) {
    int i = blockIdx.x * blockDim.x + threadIdx.x;
    if (i < N_QUADS) {
        int4 d = reinterpret_cast<const int4*>(dst)[i];
        atomicAdd(&g_deg[d.x], 1.0f);
        atomicAdd(&g_deg[d.y], 1.0f);
        atomicAdd(&g_deg[d.z], 1.0f);
        atomicAdd(&g_deg[d.w], 1.0f);
    }
}

// K3: dinv = rsqrt(deg); y = dinv*x stored f16x2; agg1 init with f32 self-loop.
__global__ void k_prescale(const float* __restrict__ x) {
    int n = blockIdx.x * blockDim.x + threadIdx.x;
    if (n < N_NODES) {
        float di = rsqrtf(g_deg[n]);
        g_dinv[n] = di;
        float2 xv = reinterpret_cast<const float2*>(x)[n];
        float2 y  = make_float2(di * xv.x, di * xv.y);
        g_y[n]    = __floats2half2_rn(y.x, y.y);
        g_agg1[n] = y;                       // self-loop in full precision
    }
}

// K4: layer-1 aggregation: agg1[d] += y[s].
__global__ void k_agg1(const int* __restrict__ src,
                       const int* __restrict__ dst) {
    int i = blockIdx.x * blockDim.x + threadIdx.x;
    if (i < N_QUADS) {
        int4 s = reinterpret_cast<const int4*>(src)[i];
        int4 d = reinterpret_cast<const int4*>(dst)[i];
        float2 y0 = __half22float2(g_y[s.x]);
        float2 y1 = __half22float2(g_y[s.y]);
        float2 y2 = __half22float2(g_y[s.z]);
        float2 y3 = __half22float2(g_y[s.w]);
        red_add_v2(&g_agg1[d.x], y0.x, y0.y);
        red_add_v2(&g_agg1[d.y], y1.x, y1.y);
        red_add_v2(&g_agg1[d.z], y2.x, y2.y);
        red_add_v2(&g_agg1[d.w], y3.x, y3.y);
    }
}

// K5: per-node fused dense chain.
//   a  = dinv[n] * agg1[n]              (destination post-scale, layer 1)
//   h  = relu(a @ W1^T + b1)            (64-dim, registers only)
//   z  = h @ W2^T                       (2-dim)
//   zs = dinv[n] * z                    (source pre-scale, layer 2)
//   out[n] = zs (f32)                   (self-loop init of layer-2 aggregation)
__global__ void k_node(const float* __restrict__ W1,
                       const float* __restrict__ b1,
                       const float* __restrict__ W2,
                       float2* __restrict__ out) {
    __shared__ float sW1[128];   // W1 row-major [64,2]
    __shared__ float sb1[64];
    __shared__ float sW2[128];   // W2 row-major [2,64]
    int t = threadIdx.x;
    if (t < 128)              sW1[t]       = W1[t];
    if (t < 64)               sb1[t]       = b1[t];
    if (t >= 128 && t < 256)  sW2[t - 128] = W2[t - 128];
    __syncthreads();

    int n = blockIdx.x * blockDim.x + t;
    if (n >= N_NODES) return;

    float  di = g_dinv[n];
    float2 ag = g_agg1[n];
    float  ax = di * ag.x, ay = di * ag.y;

    float zx = 0.0f, zy = 0.0f;
#pragma unroll
    for (int j = 0; j < 64; j++) {
        float h = fmaf(sW1[2 * j], ax, fmaf(sW1[2 * j + 1], ay, sb1[j]));
        h = fmaxf(h, 0.0f);
        zx = fmaf(sW2[j],      h, zx);
        zy = fmaf(sW2[64 + j], h, zy);
    }
    float zsx = di * zx, zsy = di * zy;
    g_zs[n] = __floats2half2_rn(zsx, zsy);
    out[n]  = make_float2(zsx, zsy);         // self-loop in full precision
}

// K6: layer-2 aggregation directly into d_out: out[d] += zs[s].
__global__ void k_agg2(const int* __restrict__ src,
                       const int* __restrict__ dst,
                       float2* __restrict__ out) {
    int i = blockIdx.x * blockDim.x + threadIdx.x;
    if (i < N_QUADS) {
        int4 s = reinterpret_cast<const int4*>(src)[i];
        int4 d = reinterpret_cast<const int4*>(dst)[i];
        float2 z0 = __half22float2(g_zs[s.x]);
        float2 z1 = __half22float2(g_zs[s.y]);
        float2 z2 = __half22float2(g_zs[s.z]);
        float2 z3 = __half22float2(g_zs[s.w]);
        red_add_v2(&out[d.x], z0.x, z0.y);
        red_add_v2(&out[d.y], z1.x, z1.y);
        red_add_v2(&out[d.z], z2.x, z2.y);
        red_add_v2(&out[d.w], z3.x, z3.y);
    }
}

// K7: destination post-scale + bias: out[n] = dinv[n]*out[n] + b2.
__global__ void k_final(const float* __restrict__ b2,
                        float2* __restrict__ out) {
    int n = blockIdx.x * blockDim.x + threadIdx.x;
    if (n < N_NODES) {
        float di = g_dinv[n];
        float2 o = out[n];
        float bb0 = __ldg(&b2[0]), bb1 = __ldg(&b2[1]);
        out[n] = make_float2(fmaf(di, o.x, bb0), fmaf(di, o.y, bb1));
    }
}

extern "C" void kernel_launch(void* const* d_in, const int* in_sizes, int n_in,
                              void* d_out, int out_size) {
    const float* x  = (const float*)d_in[0];
    const int*   ei = (const int*)d_in[1];
    const float* W1 = (const float*)d_in[2];
    const float* b1 = (const float*)d_in[3];
    const float* W2 = (const float*)d_in[4];
    const float* b2 = (const float*)d_in[5];
    float2*      out = (float2*)d_out;

    const int* src = ei;
    const int* dst = ei + N_EDGES;

    const int TB = 256;
    int nb_nodes = (N_NODES + TB - 1) / TB;
    int nb_quads = (N_QUADS + TB - 1) / TB;

    k_init    <<<nb_nodes, TB>>>();
    k_degree  <<<nb_quads, TB>>>(dst);
    k_prescale<<<nb_nodes, TB>>>(x);
    k_agg1    <<<nb_quads, TB>>>(src, dst);
    k_node    <<<nb_nodes, TB>>>(W1, b1, W2, out);
    k_agg2    <<<nb_quads, TB>>>(src, dst, out);
    k_final   <<<nb_nodes, TB>>>(b2, out);
}